// round 1
// baseline (speedup 1.0000x reference)
#include <cuda_runtime.h>

#define B_ 2
#define S_ 2048
#define D_ 1024
#define H_ 16
#define HD_ 64

// Scratch (device globals; no allocation)
__device__ float g_qkv[(size_t)B_ * S_ * 3 * D_];   // [B,S,3D]
__device__ float g_attn[(size_t)B_ * S_ * D_];      // [B,S,D]

// ---------------------------------------------------------------------------
// C[M,N] = A[M,K] @ W[K,N] + bias[N]
// 64x64 tile, BK=16, 256 threads, 4x4 micro-tile per thread.
// ---------------------------------------------------------------------------
__global__ __launch_bounds__(256) void gemm_bias_kernel(
    const float* __restrict__ A, const float* __restrict__ W,
    const float* __restrict__ bias, float* __restrict__ C,
    int M, int N, int K)
{
    __shared__ float As[64][17];
    __shared__ float Bs[16][64];

    const int t  = threadIdx.x;
    const int tx = t & 15;
    const int ty = t >> 4;
    const int row0 = blockIdx.y * 64;
    const int col0 = blockIdx.x * 64;

    float acc[4][4] = {};

    for (int k0 = 0; k0 < K; k0 += 16) {
        // Load A tile 64x16 (float4 per thread)
        {
            int r = t >> 2;
            int c = (t & 3) << 2;
            float4 a4 = *reinterpret_cast<const float4*>(
                A + (size_t)(row0 + r) * K + k0 + c);
            As[r][c + 0] = a4.x; As[r][c + 1] = a4.y;
            As[r][c + 2] = a4.z; As[r][c + 3] = a4.w;
        }
        // Load W tile 16x64 (float4 per thread)
        {
            int r = t >> 4;
            int c = (t & 15) << 2;
            *reinterpret_cast<float4*>(&Bs[r][c]) =
                *reinterpret_cast<const float4*>(
                    W + (size_t)(k0 + r) * N + col0 + c);
        }
        __syncthreads();

#pragma unroll
        for (int kk = 0; kk < 16; kk++) {
            float a[4], b[4];
#pragma unroll
            for (int i = 0; i < 4; i++) a[i] = As[ty * 4 + i][kk];
#pragma unroll
            for (int j = 0; j < 4; j++) b[j] = Bs[kk][tx * 4 + j];
#pragma unroll
            for (int i = 0; i < 4; i++)
#pragma unroll
                for (int j = 0; j < 4; j++)
                    acc[i][j] = fmaf(a[i], b[j], acc[i][j]);
        }
        __syncthreads();
    }

#pragma unroll
    for (int j = 0; j < 4; j++) {
        float bj = bias[col0 + tx * 4 + j];
#pragma unroll
        for (int i = 0; i < 4; i++)
            C[(size_t)(row0 + ty * 4 + i) * N + col0 + tx * 4 + j] =
                acc[i][j] + bj;
    }
}

// ---------------------------------------------------------------------------
// Flash-style attention over g_qkv -> g_attn.
// Block: 64 queries of one (b,h). Key blocks of 32. Online softmax.
// Thread (ty,tx): score tile rows ty*4+[0..3], cols tx*2+[0..1];
//                 output tile rows ty*4+[0..3], dims tx*4+[0..3].
// ---------------------------------------------------------------------------
__global__ __launch_bounds__(256) void attn_kernel()
{
    __shared__ float sQ[64][65];
    __shared__ float sK[32][65];
    __shared__ float sV[32][68];   // pad 68 so float4 reads stay aligned
    __shared__ float sP[64][33];

    const int t  = threadIdx.x;
    const int tx = t & 15;
    const int ty = t >> 4;
    const int qb = blockIdx.x;
    const int h  = blockIdx.y;
    const int b  = blockIdx.z;

    const size_t rowstride = 3 * D_;
    const size_t qoff = (size_t)(b * S_) * rowstride + (size_t)h * HD_;
    const size_t koff = qoff + D_;
    const size_t voff = qoff + 2 * D_;

    // Load Q block 64x64
#pragma unroll
    for (int i = 0; i < 4; i++) {
        int idx4 = t + 256 * i;          // 0..1023
        int r = idx4 >> 4;               // 0..63
        int c = (idx4 & 15) << 2;        // 0..60
        float4 q4 = *reinterpret_cast<const float4*>(
            g_qkv + qoff + (size_t)(qb * 64 + r) * rowstride + c);
        sQ[r][c + 0] = q4.x; sQ[r][c + 1] = q4.y;
        sQ[r][c + 2] = q4.z; sQ[r][c + 3] = q4.w;
    }

    float o[4][4] = {};
    float m[4], l[4];
#pragma unroll
    for (int i = 0; i < 4; i++) { m[i] = -1e30f; l[i] = 0.0f; }

    const float scale = 0.125f;  // 1/sqrt(64)

    for (int kb = 0; kb < S_ / 32; kb++) {
        __syncthreads();   // protect sK/sV/sP from previous iteration

        // Load K,V blocks 32x64
#pragma unroll
        for (int i = 0; i < 2; i++) {
            int idx4 = t + 256 * i;      // 0..511
            int r = idx4 >> 4;           // 0..31
            int c = (idx4 & 15) << 2;    // 0..60
            size_t g = (size_t)(kb * 32 + r) * rowstride + c;
            float4 k4 = *reinterpret_cast<const float4*>(g_qkv + koff + g);
            sK[r][c + 0] = k4.x; sK[r][c + 1] = k4.y;
            sK[r][c + 2] = k4.z; sK[r][c + 3] = k4.w;
            float4 v4 = *reinterpret_cast<const float4*>(g_qkv + voff + g);
            *reinterpret_cast<float4*>(&sV[r][c]) = v4;
        }
        __syncthreads();

        // Scores: s[4][2] = Q(4 rows) . K^T(2 cols)
        float s[4][2] = {};
#pragma unroll
        for (int d = 0; d < 64; d++) {
            float q0 = sQ[ty * 4 + 0][d];
            float q1 = sQ[ty * 4 + 1][d];
            float q2 = sQ[ty * 4 + 2][d];
            float q3 = sQ[ty * 4 + 3][d];
            float k0 = sK[tx * 2 + 0][d];
            float k1 = sK[tx * 2 + 1][d];
            s[0][0] = fmaf(q0, k0, s[0][0]); s[0][1] = fmaf(q0, k1, s[0][1]);
            s[1][0] = fmaf(q1, k0, s[1][0]); s[1][1] = fmaf(q1, k1, s[1][1]);
            s[2][0] = fmaf(q2, k0, s[2][0]); s[2][1] = fmaf(q2, k1, s[2][1]);
            s[3][0] = fmaf(q3, k0, s[3][0]); s[3][1] = fmaf(q3, k1, s[3][1]);
        }

        // Online softmax update per row
#pragma unroll
        for (int i = 0; i < 4; i++) {
            float s0 = s[i][0] * scale;
            float s1 = s[i][1] * scale;
            float mloc = fmaxf(s0, s1);
#pragma unroll
            for (int off = 1; off < 16; off <<= 1)
                mloc = fmaxf(mloc, __shfl_xor_sync(0xffffffffu, mloc, off));
            float mn = fmaxf(m[i], mloc);
            float alpha = __expf(m[i] - mn);
            float p0 = __expf(s0 - mn);
            float p1 = __expf(s1 - mn);
            float lsum = p0 + p1;
#pragma unroll
            for (int off = 1; off < 16; off <<= 1)
                lsum += __shfl_xor_sync(0xffffffffu, lsum, off);
            l[i] = l[i] * alpha + lsum;
            m[i] = mn;
#pragma unroll
            for (int j = 0; j < 4; j++) o[i][j] *= alpha;
            sP[ty * 4 + i][tx * 2 + 0] = p0;
            sP[ty * 4 + i][tx * 2 + 1] = p1;
        }
        __syncthreads();

        // O += P @ V
#pragma unroll
        for (int c = 0; c < 32; c++) {
            float4 v4 = *reinterpret_cast<const float4*>(&sV[c][tx * 4]);
            float p0 = sP[ty * 4 + 0][c];
            float p1 = sP[ty * 4 + 1][c];
            float p2 = sP[ty * 4 + 2][c];
            float p3 = sP[ty * 4 + 3][c];
            o[0][0] = fmaf(p0, v4.x, o[0][0]); o[0][1] = fmaf(p0, v4.y, o[0][1]);
            o[0][2] = fmaf(p0, v4.z, o[0][2]); o[0][3] = fmaf(p0, v4.w, o[0][3]);
            o[1][0] = fmaf(p1, v4.x, o[1][0]); o[1][1] = fmaf(p1, v4.y, o[1][1]);
            o[1][2] = fmaf(p1, v4.z, o[1][2]); o[1][3] = fmaf(p1, v4.w, o[1][3]);
            o[2][0] = fmaf(p2, v4.x, o[2][0]); o[2][1] = fmaf(p2, v4.y, o[2][1]);
            o[2][2] = fmaf(p2, v4.z, o[2][2]); o[2][3] = fmaf(p2, v4.w, o[2][3]);
            o[3][0] = fmaf(p3, v4.x, o[3][0]); o[3][1] = fmaf(p3, v4.y, o[3][1]);
            o[3][2] = fmaf(p3, v4.z, o[3][2]); o[3][3] = fmaf(p3, v4.w, o[3][3]);
        }
    }

    // Normalize and write to g_attn [B,S,D] (heads re-interleaved)
#pragma unroll
    for (int i = 0; i < 4; i++) {
        float inv = 1.0f / l[i];
        int srow = qb * 64 + ty * 4 + i;
        float* op = g_attn + ((size_t)(b * S_ + srow) * D_) + h * HD_ + tx * 4;
        op[0] = o[i][0] * inv;
        op[1] = o[i][1] * inv;
        op[2] = o[i][2] * inv;
        op[3] = o[i][3] * inv;
    }
}

// ---------------------------------------------------------------------------
extern "C" void kernel_launch(void* const* d_in, const int* in_sizes, int n_in,
                              void* d_out, int out_size)
{
    const float* x      = (const float*)d_in[0];
    const float* w_qkv  = (const float*)d_in[1];
    const float* b_qkv  = (const float*)d_in[2];
    const float* w_proj = (const float*)d_in[3];
    const float* b_proj = (const float*)d_in[4];
    float* out = (float*)d_out;

    float* qkv_p  = nullptr;
    float* attn_p = nullptr;
    cudaGetSymbolAddress((void**)&qkv_p,  g_qkv);
    cudaGetSymbolAddress((void**)&attn_p, g_attn);

    const int M = B_ * S_;           // 4096

    // QKV GEMM: [4096,1024] @ [1024,3072] + bias
    gemm_bias_kernel<<<dim3((3 * D_) / 64, M / 64), 256>>>(
        x, w_qkv, b_qkv, qkv_p, M, 3 * D_, D_);

    // Attention
    attn_kernel<<<dim3(S_ / 64, H_, B_), 256>>>();

    // Projection GEMM: [4096,1024] @ [1024,1024] + bias
    gemm_bias_kernel<<<dim3(D_ / 64, M / 64), 256>>>(
        attn_p, w_proj, b_proj, out, M, D_, D_);
}

// round 4
// speedup vs baseline: 2.8935x; 2.8935x over previous
#include <cuda_runtime.h>
#include <cuda_fp16.h>
#include <cstdint>

#define B_ 2
#define S_ 2048
#define D_ 1024
#define H_ 16
#define HD_ 64
#define M_TOT 4096
#define KEFF 3072          // 3 * 1024  (fp16 hi/lo split concat)
#define NKITER 48          // KEFF / 64
#define LOG2E 1.44269504f

// ---------------------------------------------------------------------------
// Scratch (device globals; no allocation)
// ---------------------------------------------------------------------------
__device__ __half g_a1[(size_t)M_TOT * KEFF];          // x split [hi|lo|hi]
__device__ __half g_a2[(size_t)M_TOT * KEFF];          // attn-out split [hi|lo|hi]
__device__ __half g_wqkvT[(size_t)(3 * D_) * KEFF];    // w_qkv^T split [hi|hi|lo]
__device__ __half g_wprojT[(size_t)D_ * KEFF];         // w_proj^T split [hi|hi|lo]
__device__ __half g_Q[(size_t)B_ * H_ * S_ * 192];     // scaled q split [hi|lo|hi]
__device__ __half g_K[(size_t)B_ * H_ * S_ * 192];     // k split [hi|hi|lo]
__device__ __half g_Vhi[(size_t)B_ * H_ * S_ * 64];
__device__ __half g_Vlo[(size_t)B_ * H_ * S_ * 64];

// ---------------------------------------------------------------------------
// PTX helpers
// ---------------------------------------------------------------------------
__device__ __forceinline__ uint32_t smem_u32(const void* p) {
    uint32_t a;
    asm("{ .reg .u64 t; cvta.to.shared.u64 t, %1; cvt.u32.u64 %0, t; }"
        : "=r"(a) : "l"(p));
    return a;
}
#define CP_ASYNC16(dst, src) \
    asm volatile("cp.async.cg.shared.global [%0], [%1], 16;" \
                 :: "r"(dst), "l"(src))
#define CP_COMMIT() asm volatile("cp.async.commit_group;")
#define CP_WAIT(n)  asm volatile("cp.async.wait_group %0;" :: "n"(n))

__device__ __forceinline__ void ldsm_x4(uint32_t& r0, uint32_t& r1,
                                        uint32_t& r2, uint32_t& r3,
                                        uint32_t addr) {
    asm volatile("ldmatrix.sync.aligned.m8n8.x4.shared.b16 {%0,%1,%2,%3}, [%4];"
                 : "=r"(r0), "=r"(r1), "=r"(r2), "=r"(r3) : "r"(addr));
}
__device__ __forceinline__ void ldsm_x4_t(uint32_t& r0, uint32_t& r1,
                                          uint32_t& r2, uint32_t& r3,
                                          uint32_t addr) {
    asm volatile("ldmatrix.sync.aligned.m8n8.x4.trans.shared.b16 {%0,%1,%2,%3}, [%4];"
                 : "=r"(r0), "=r"(r1), "=r"(r2), "=r"(r3) : "r"(addr));
}
__device__ __forceinline__ void mma16816(float* c, const uint32_t* a,
                                         uint32_t b0, uint32_t b1) {
    asm volatile(
        "mma.sync.aligned.m16n8k16.row.col.f32.f16.f16.f32 "
        "{%0,%1,%2,%3}, {%4,%5,%6,%7}, {%8,%9}, {%0,%1,%2,%3};"
        : "+f"(c[0]), "+f"(c[1]), "+f"(c[2]), "+f"(c[3])
        : "r"(a[0]), "r"(a[1]), "r"(a[2]), "r"(a[3]), "r"(b0), "r"(b1));
}

__device__ __forceinline__ float fexp2(float t) {
    t = fmaxf(t, -126.0f);
    float z = t + 12582912.0f;                 // round-to-nearest int
    int ii = __float_as_int(z) - 0x4B400000;
    float f = t - (z - 12582912.0f);           // f in [-0.5, 0.5]
    float p = 1.33336e-3f;
    p = fmaf(p, f, 9.61813e-3f);
    p = fmaf(p, f, 5.550411e-2f);
    p = fmaf(p, f, 2.4022651e-1f);
    p = fmaf(p, f, 6.9314718e-1f);
    p = fmaf(p, f, 1.0f);
    return p * __int_as_float((ii + 127) << 23);
}

__device__ __forceinline__ uint32_t packh2(float a, float b) {
    __half2 h = __floats2half2_rn(a, b);
    return *reinterpret_cast<uint32_t*>(&h);
}

// ---------------------------------------------------------------------------
// fp16 split conversion kernels
// ---------------------------------------------------------------------------
__global__ __launch_bounds__(256) void split_a_kernel(
    const float* __restrict__ src, __half* __restrict__ dst)
{
    int i = blockIdx.x * 256 + threadIdx.x;    // over 4096*1024
    float v = src[i];
    __half hi = __float2half_rn(v);
    __half lo = __float2half_rn(v - __half2float(hi));
    int row = i >> 10;
    int col = i & 1023;
    size_t base = (size_t)row * KEFF;
    dst[base + col] = hi;
    dst[base + 1024 + col] = lo;
    dst[base + 2048 + col] = hi;
}

__global__ __launch_bounds__(256) void transpose_split_kernel(
    const float* __restrict__ w, __half* __restrict__ wt, int N)
{
    __shared__ float tile[32][33];
    int bx = blockIdx.x * 32;   // n base
    int by = blockIdx.y * 32;   // k base
    int tx = threadIdx.x;       // 32
    int ty = threadIdx.y;       // 8
#pragma unroll
    for (int i = ty; i < 32; i += 8)
        tile[i][tx] = w[(size_t)(by + i) * N + bx + tx];
    __syncthreads();
#pragma unroll
    for (int i = ty; i < 32; i += 8) {
        int n = bx + i;
        int k = by + tx;
        float v = tile[tx][i];
        __half hi = __float2half_rn(v);
        __half lo = __float2half_rn(v - __half2float(hi));
        size_t base = (size_t)n * KEFF;
        wt[base + k] = hi;
        wt[base + 1024 + k] = hi;
        wt[base + 2048 + k] = lo;
    }
}

// ---------------------------------------------------------------------------
// HMMA GEMM: C[m,n] = sum_k A[m,k]*Bt[n,k] (+bias).  A:[M,KEFF] Bt:[N,KEFF] fp16.
// CTA 128x128, BK=64, 2-stage cp.async, 256 thr = 8 warps (2m x 4n), warp 64x32.
// EPI==0: fp32 C + bias.  EPI==1: QKV epilogue -> split g_Q/g_K/g_Vhi/g_Vlo.
// ---------------------------------------------------------------------------
#define GEMM_SMEM (4 * 16384)

template <int EPI>
__global__ __launch_bounds__(256) void gemm_hmma_kernel(
    const __half* __restrict__ A, const __half* __restrict__ Bt,
    const float* __restrict__ bias, float* __restrict__ C, int N)
{
    extern __shared__ char smem[];
    const uint32_t sbase = smem_u32(smem);
    const int t = threadIdx.x;
    const int lane = t & 31;
    const int wid = t >> 5;
    const int wm = wid >> 2;          // 0..1
    const int wn = wid & 3;           // 0..3
    const int row0 = blockIdx.y * 128;
    const int col0 = blockIdx.x * 128;

    const __half* Ag = A + (size_t)row0 * KEFF;
    const __half* Bg = Bt + (size_t)col0 * KEFF;

    float c[4][4][4];
#pragma unroll
    for (int i = 0; i < 4; i++)
#pragma unroll
        for (int j = 0; j < 4; j++)
#pragma unroll
            for (int r = 0; r < 4; r++) c[i][j][r] = 0.0f;

    auto load_stage = [&](int kb, int st) {
        uint32_t sa = sbase + st * 16384;
        uint32_t sb = sbase + 32768 + st * 16384;
#pragma unroll
        for (int i = 0; i < 4; i++) {
            int id = t + 256 * i;
            int r = id >> 3;
            int u = id & 7;
            uint32_t sw = (uint32_t)(r * 128 + ((u ^ (r & 7)) << 4));
            CP_ASYNC16(sa + sw, Ag + (size_t)r * KEFF + kb * 64 + u * 8);
            CP_ASYNC16(sb + sw, Bg + (size_t)r * KEFF + kb * 64 + u * 8);
        }
    };

    load_stage(0, 0);
    CP_COMMIT();

    const int mat = lane >> 3;
    const int wi = lane & 7;

    for (int kb = 0; kb < NKITER; kb++) {
        int cur = kb & 1;
        if (kb + 1 < NKITER) {
            load_stage(kb + 1, cur ^ 1);
            CP_COMMIT();
            CP_WAIT(1);
        } else {
            CP_WAIT(0);
        }
        __syncthreads();

        uint32_t sa = sbase + cur * 16384;
        uint32_t sb = sbase + 32768 + cur * 16384;

#pragma unroll
        for (int s = 0; s < 4; s++) {
            uint32_t a[4][4];
#pragma unroll
            for (int mi = 0; mi < 4; mi++) {
                int row = wm * 64 + mi * 16 + (mat & 1) * 8 + wi;
                int u = 2 * s + (mat >> 1);
                ldsm_x4(a[mi][0], a[mi][1], a[mi][2], a[mi][3],
                        sa + row * 128 + (((u ^ wi) & 7) << 4));
            }
            uint32_t b[2][4];
#pragma unroll
            for (int j = 0; j < 2; j++) {
                int row = wn * 32 + j * 16 + (mat & 1) * 8 + wi;
                int u = 2 * s + (mat >> 1);
                ldsm_x4(b[j][0], b[j][1], b[j][2], b[j][3],
                        sb + row * 128 + (((u ^ wi) & 7) << 4));
            }
#pragma unroll
            for (int mi = 0; mi < 4; mi++)
#pragma unroll
                for (int nn = 0; nn < 4; nn++)
                    mma16816(c[mi][nn], a[mi],
                             b[nn >> 1][nn & 1], b[nn >> 1][(nn & 1) + 2]);
        }
        __syncthreads();
    }

    // Epilogue
#pragma unroll
    for (int mi = 0; mi < 4; mi++) {
#pragma unroll
        for (int nn = 0; nn < 4; nn++) {
#pragma unroll
            for (int rp = 0; rp < 2; rp++) {
                int m = row0 + wm * 64 + mi * 16 + (lane >> 2) + rp * 8;
                int n = col0 + wn * 32 + nn * 8 + (lane & 3) * 2;
                float v0 = c[mi][nn][rp * 2 + 0] + bias[n];
                float v1 = c[mi][nn][rp * 2 + 1] + bias[n + 1];
                if (EPI == 0) {
                    float2 v = make_float2(v0, v1);
                    *reinterpret_cast<float2*>(C + (size_t)m * N + n) = v;
                } else {
                    int type = n >> 10;
                    int rr = n & 1023;
                    int h = rr >> 6;
                    int d = rr & 63;
                    int b = m >> 11;
                    int s = m & 2047;
                    if (type == 0) { v0 *= 0.125f; v1 *= 0.125f; }  // fold 1/sqrt(64)
                    __half h0 = __float2half_rn(v0);
                    __half h1 = __float2half_rn(v1);
                    __half l0 = __float2half_rn(v0 - __half2float(h0));
                    __half l1 = __float2half_rn(v1 - __half2float(h1));
                    __half2 hh = __halves2half2(h0, h1);
                    __half2 ll = __halves2half2(l0, l1);
                    size_t hb = (size_t)(b * H_ + h) * S_ + s;
                    if (type == 0) {            // Q: [hi|lo|hi]
                        __half* p = g_Q + hb * 192 + d;
                        *reinterpret_cast<__half2*>(p)       = hh;
                        *reinterpret_cast<__half2*>(p + 64)  = ll;
                        *reinterpret_cast<__half2*>(p + 128) = hh;
                    } else if (type == 1) {     // K: [hi|hi|lo]
                        __half* p = g_K + hb * 192 + d;
                        *reinterpret_cast<__half2*>(p)       = hh;
                        *reinterpret_cast<__half2*>(p + 64)  = hh;
                        *reinterpret_cast<__half2*>(p + 128) = ll;
                    } else {                    // V: hi / lo arrays
                        *reinterpret_cast<__half2*>(g_Vhi + hb * 64 + d) = hh;
                        *reinterpret_cast<__half2*>(g_Vlo + hb * 64 + d) = ll;
                    }
                }
            }
        }
    }
}

// ---------------------------------------------------------------------------
// Flash attention (HMMA): q-tile 128, key blocks of 64, 256 thr = 8 warps
// (warp w owns q-rows 16w..16w+15).  Scores over K=192 (split).  P@V as
// 3 passes (Phi*Vhi + Phi*Vlo + Plo*Vhi).  Output -> g_a2 split [hi|lo|hi].
// ---------------------------------------------------------------------------
#define FA_SMEM (49152 + 49152 + 32768)   // Q + 2*K + 2*V = 131072

__global__ __launch_bounds__(256) void flash_kernel(__half* __restrict__ a2out)
{
    extern __shared__ char smem[];
    const uint32_t sQ = smem_u32(smem);
    const uint32_t sK0 = sQ + 49152;
    const uint32_t sV0 = sK0 + 49152;
    const int t = threadIdx.x;
    const int lane = t & 31;
    const int wid = t >> 5;
    const int qb = blockIdx.x;    // 0..15
    const int h = blockIdx.y;     // 0..15
    const int b = blockIdx.z;     // 0..1

    const size_t headbase = (size_t)(b * H_ + h) * S_;
    const __half* Qg = g_Q + (headbase + qb * 128) * 192;
    const __half* Kg = g_K + headbase * 192;
    const __half* Vh = g_Vhi + headbase * 64;
    const __half* Vl = g_Vlo + headbase * 64;

    // Load Q tile (128 x 192 fp16, 384B rows, swizzled)
#pragma unroll
    for (int i = 0; i < 12; i++) {
        int id = t + 256 * i;
        int r = id / 24;
        int u = id % 24;
        int swu = (u & 24) | ((u ^ r) & 7);
        CP_ASYNC16(sQ + r * 384 + swu * 16, Qg + (size_t)r * 192 + u * 8);
    }

    auto loadKV = [&](int kb, int st) {
        uint32_t sk = sK0 + st * 24576;
        uint32_t sv = sV0 + st * 16384;
        const __half* kg = Kg + (size_t)kb * 64 * 192;
#pragma unroll
        for (int i = 0; i < 6; i++) {
            int id = t + 256 * i;
            int r = id / 24;
            int u = id % 24;
            int swu = (u & 24) | ((u ^ r) & 7);
            CP_ASYNC16(sk + r * 384 + swu * 16, kg + (size_t)r * 192 + u * 8);
        }
        const __half* vh = Vh + (size_t)kb * 64 * 64;
        const __half* vl = Vl + (size_t)kb * 64 * 64;
#pragma unroll
        for (int i = 0; i < 2; i++) {
            int id = t + 256 * i;
            int r = id >> 3;
            int u = id & 7;
            int swu = u ^ (r & 7);
            CP_ASYNC16(sv + r * 128 + swu * 16, vh + (size_t)r * 64 + u * 8);
            CP_ASYNC16(sv + 8192 + r * 128 + swu * 16, vl + (size_t)r * 64 + u * 8);
        }
    };

    loadKV(0, 0);
    CP_COMMIT();

    float o[8][4];
#pragma unroll
    for (int i = 0; i < 8; i++)
#pragma unroll
        for (int j = 0; j < 4; j++) o[i][j] = 0.0f;
    float m0 = -1e30f, m1 = -1e30f, l0 = 0.0f, l1 = 0.0f;

    const int mat = lane >> 3;
    const int wi = lane & 7;

    for (int kb = 0; kb < 32; kb++) {
        int st = kb & 1;
        if (kb + 1 < 32) {
            loadKV(kb + 1, st ^ 1);
            CP_COMMIT();
            CP_WAIT(1);
        } else {
            CP_WAIT(0);
        }
        __syncthreads();

        // ---- scores: S = Qtile(16x192) @ K'(64x192)^T ----
        float s[8][4];
#pragma unroll
        for (int i = 0; i < 8; i++)
#pragma unroll
            for (int j = 0; j < 4; j++) s[i][j] = 0.0f;

        uint32_t skb = sK0 + st * 24576;
#pragma unroll
        for (int ks = 0; ks < 12; ks++) {
            uint32_t a[4];
            {
                int row = wid * 16 + (mat & 1) * 8 + wi;
                int u = 2 * ks + (mat >> 1);
                int swu = (u & 24) | ((u ^ row) & 7);
                ldsm_x4(a[0], a[1], a[2], a[3], sQ + row * 384 + swu * 16);
            }
#pragma unroll
            for (int j = 0; j < 4; j++) {
                uint32_t bb[4];
                int row = j * 16 + (mat & 1) * 8 + wi;
                int u = 2 * ks + (mat >> 1);
                int swu = (u & 24) | ((u ^ row) & 7);
                ldsm_x4(bb[0], bb[1], bb[2], bb[3], skb + row * 384 + swu * 16);
                mma16816(s[j * 2 + 0], a, bb[0], bb[2]);
                mma16816(s[j * 2 + 1], a, bb[1], bb[3]);
            }
        }

        // ---- online softmax (rows r0 = wid*16 + lane/4, r1 = r0+8) ----
        float nm0 = -1e30f, nm1 = -1e30f;
#pragma unroll
        for (int nn = 0; nn < 8; nn++) {
            nm0 = fmaxf(nm0, fmaxf(s[nn][0], s[nn][1]));
            nm1 = fmaxf(nm1, fmaxf(s[nn][2], s[nn][3]));
        }
        nm0 = fmaxf(nm0, __shfl_xor_sync(0xffffffffu, nm0, 1));
        nm0 = fmaxf(nm0, __shfl_xor_sync(0xffffffffu, nm0, 2));
        nm1 = fmaxf(nm1, __shfl_xor_sync(0xffffffffu, nm1, 1));
        nm1 = fmaxf(nm1, __shfl_xor_sync(0xffffffffu, nm1, 2));
        nm0 = fmaxf(nm0, m0);
        nm1 = fmaxf(nm1, m1);
        float al0 = fexp2((m0 - nm0) * LOG2E);
        float al1 = fexp2((m1 - nm1) * LOG2E);
        m0 = nm0;
        m1 = nm1;

        float sum0 = 0.0f, sum1 = 0.0f;
        uint32_t ph0[8], ph1[8], pl0[8], pl1[8];
#pragma unroll
        for (int nn = 0; nn < 8; nn++) {
            float p00 = fexp2((s[nn][0] - m0) * LOG2E);
            float p01 = fexp2((s[nn][1] - m0) * LOG2E);
            float p10 = fexp2((s[nn][2] - m1) * LOG2E);
            float p11 = fexp2((s[nn][3] - m1) * LOG2E);
            sum0 += p00 + p01;
            sum1 += p10 + p11;
            ph0[nn] = packh2(p00, p01);
            ph1[nn] = packh2(p10, p11);
            __half2 h0 = *reinterpret_cast<__half2*>(&ph0[nn]);
            __half2 h1 = *reinterpret_cast<__half2*>(&ph1[nn]);
            pl0[nn] = packh2(p00 - __low2float(h0), p01 - __high2float(h0));
            pl1[nn] = packh2(p10 - __low2float(h1), p11 - __high2float(h1));
        }
        sum0 += __shfl_xor_sync(0xffffffffu, sum0, 1);
        sum0 += __shfl_xor_sync(0xffffffffu, sum0, 2);
        sum1 += __shfl_xor_sync(0xffffffffu, sum1, 1);
        sum1 += __shfl_xor_sync(0xffffffffu, sum1, 2);
        l0 = l0 * al0 + sum0;
        l1 = l1 * al1 + sum1;
#pragma unroll
        for (int nn = 0; nn < 8; nn++) {
            o[nn][0] *= al0;
            o[nn][1] *= al0;
            o[nn][2] *= al1;
            o[nn][3] *= al1;
        }

        // ---- O += P' @ V'  (3 passes: Phi*Vhi, Phi*Vlo, Plo*Vhi) ----
        uint32_t sv = sV0 + st * 16384;
#pragma unroll
        for (int pass = 0; pass < 3; pass++) {
            const uint32_t* A0 = (pass == 2) ? pl0 : ph0;
            const uint32_t* A1 = (pass == 2) ? pl1 : ph1;
            uint32_t vb = (pass == 1) ? sv + 8192 : sv;
#pragma unroll
            for (int ks = 0; ks < 4; ks++) {
                uint32_t a[4] = { A0[2 * ks], A1[2 * ks],
                                  A0[2 * ks + 1], A1[2 * ks + 1] };
#pragma unroll
                for (int j = 0; j < 4; j++) {
                    uint32_t bb[4];
                    int krow = ks * 16 + (mat & 1) * 8 + wi;
                    int u = j * 2 + (mat >> 1);
                    int swu = u ^ (krow & 7);
                    ldsm_x4_t(bb[0], bb[1], bb[2], bb[3],
                              vb + krow * 128 + swu * 16);
                    mma16816(o[j * 2 + 0], a, bb[0], bb[1]);
                    mma16816(o[j * 2 + 1], a, bb[2], bb[3]);
                }
            }
        }
        __syncthreads();
    }

    // ---- epilogue: normalize and write split proj input ----
    float inv0 = 1.0f / l0;
    float inv1 = 1.0f / l1;
    int s0 = qb * 128 + wid * 16 + (lane >> 2);
    int s1 = s0 + 8;
#pragma unroll
    for (int nn = 0; nn < 8; nn++) {
        int d = h * 64 + nn * 8 + (lane & 3) * 2;
#pragma unroll
        for (int rp = 0; rp < 2; rp++) {
            int srow = rp ? s1 : s0;
            float inv = rp ? inv1 : inv0;
            float v0 = o[nn][rp * 2 + 0] * inv;
            float v1 = o[nn][rp * 2 + 1] * inv;
            __half h0 = __float2half_rn(v0);
            __half h1 = __float2half_rn(v1);
            __half l0h = __float2half_rn(v0 - __half2float(h0));
            __half l1h = __float2half_rn(v1 - __half2float(h1));
            __half* p = a2out + (size_t)(b * S_ + srow) * KEFF + d;
            *reinterpret_cast<__half2*>(p)        = __halves2half2(h0, h1);
            *reinterpret_cast<__half2*>(p + 1024) = __halves2half2(l0h, l1h);
            *reinterpret_cast<__half2*>(p + 2048) = __halves2half2(h0, h1);
        }
    }
}

// ---------------------------------------------------------------------------
extern "C" void kernel_launch(void* const* d_in, const int* in_sizes, int n_in,
                              void* d_out, int out_size)
{
    const float* x      = (const float*)d_in[0];
    const float* w_qkv  = (const float*)d_in[1];
    const float* b_qkv  = (const float*)d_in[2];
    const float* w_proj = (const float*)d_in[3];
    const float* b_proj = (const float*)d_in[4];
    float* out = (float*)d_out;

    __half *a1_p, *a2_p, *wq_p, *wp_p;
    cudaGetSymbolAddress((void**)&a1_p, g_a1);
    cudaGetSymbolAddress((void**)&a2_p, g_a2);
    cudaGetSymbolAddress((void**)&wq_p, g_wqkvT);
    cudaGetSymbolAddress((void**)&wp_p, g_wprojT);

    cudaFuncSetAttribute(gemm_hmma_kernel<0>,
                         cudaFuncAttributeMaxDynamicSharedMemorySize, GEMM_SMEM);
    cudaFuncSetAttribute(gemm_hmma_kernel<1>,
                         cudaFuncAttributeMaxDynamicSharedMemorySize, GEMM_SMEM);
    cudaFuncSetAttribute(flash_kernel,
                         cudaFuncAttributeMaxDynamicSharedMemorySize, FA_SMEM);

    // 1) splits
    split_a_kernel<<<(M_TOT * D_) / 256, 256>>>(x, a1_p);
    transpose_split_kernel<<<dim3((3 * D_) / 32, D_ / 32), dim3(32, 8)>>>(
        w_qkv, wq_p, 3 * D_);
    transpose_split_kernel<<<dim3(D_ / 32, D_ / 32), dim3(32, 8)>>>(
        w_proj, wp_p, D_);

    // 2) QKV GEMM (epilogue writes split/scaled Q,K,V directly)
    gemm_hmma_kernel<1><<<dim3((3 * D_) / 128, M_TOT / 128), 256, GEMM_SMEM>>>(
        a1_p, wq_p, b_qkv, nullptr, 3 * D_);

    // 3) flash attention (epilogue writes split proj input)
    flash_kernel<<<dim3(S_ / 128, H_, B_), 256, FA_SMEM>>>(a2_p);

    // 4) projection GEMM
    gemm_hmma_kernel<0><<<dim3(D_ / 128, M_TOT / 128), 256, GEMM_SMEM>>>(
        a2_p, wp_p, b_proj, out, D_);
}